// round 12
// baseline (speedup 1.0000x reference)
#include <cuda_runtime.h>
#include <cuda_fp16.h>

// Problem constants
#define Cc 3
#define Hh 512
#define Ww 512
#define NPIX (Hh*Ww)          // 262144
#define MAXB 64

// Tile config: 64 wide x 32 tall, 256 threads, each thread 4w x 2h x 3co
#define TW 64
#define TH 32
#define SW (TW+2)             // 66
#define SH (TH+2)             // 34
#define NB_X (Ww/TW)          // 8
#define NB_Y (Hh/TH)          // 16
#define NPB (NB_X*NB_Y)       // 128 partials per image
#define NBLK_MAX (NPB*MAXB)   // 8192

// Scratch (fp16 intermediates)
__device__ __half g_y1[(size_t)MAXB*Cc*NPIX];
__device__ __half g_y2[(size_t)MAXB*Cc*NPIX];
__device__ float g_part1[NBLK_MAX*6];
__device__ float g_part2[NBLK_MAX*6];
__device__ float g_bn1[6];
__device__ float g_bn2[6];
__device__ unsigned int g_cnt[2] = {0u, 0u};

// ---- packed f32x2 helpers ----
typedef unsigned long long u64t;
__device__ __forceinline__ u64t pk2(float lo, float hi) {
    u64t r; asm("mov.b64 %0,{%1,%2};" : "=l"(r) : "f"(lo), "f"(hi)); return r;
}
__device__ __forceinline__ void upk2(u64t v, float& lo, float& hi) {
    asm("mov.b64 {%0,%1}, %2;" : "=f"(lo), "=f"(hi) : "l"(v));
}
__device__ __forceinline__ u64t fma2(u64t a, u64t b, u64t c) {
    u64t d; asm("fma.rn.f32x2 %0,%1,%2,%3;" : "=l"(d) : "l"(a), "l"(b), "l"(c)); return d;
}
__device__ __forceinline__ u64t add2(u64t a, u64t b) {
    u64t d; asm("add.rn.f32x2 %0,%1,%2;" : "=l"(d) : "l"(a), "l"(b)); return d;
}

__device__ __forceinline__ float ratf(float x,
    float a0, float a1, float a2, float a3, float a4, float a5,
    float b0, float b1, float b2, float b3)
{
    float P = fmaf(x, fmaf(x, fmaf(x, fmaf(x, fmaf(x, a5, a4), a3), a2), a1), a0);
    float q = fmaf(x, fmaf(x, fmaf(x, b3, b2), b1), b0);
    float Q = 1.0f + fabsf(x * q);
    return __fdividef(P, Q);
}

// Fused conv3x3 (+ optional BN1-affine + rational on input, in-bounds only)
// + stats + last-block BN fold (no separate reducer kernels).
template<bool PRE>
__global__ __launch_bounds__(256, 5)
void conv_kernel(const float* __restrict__ xin, const float* __restrict__ w,
                 const float* __restrict__ ar, const float* __restrict__ br,
                 const float* __restrict__ ag, const float* __restrict__ bg,
                 const float* __restrict__ ab, const float* __restrict__ bb,
                 const float* __restrict__ gamma, const float* __restrict__ beta,
                 int nblk, double invN)
{
    __shared__ float s[Cc][SH][SW];
    __shared__ u64t swp[81];          // packed weights [ci][ky][kx][co]
    __shared__ float sred[8][6];
    __shared__ bool isLast;

    const int b  = blockIdx.z;
    const int h0 = blockIdx.y * TH;
    const int w0 = blockIdx.x * TW;
    const int tid = threadIdx.x;

    __half* outbuf = PRE ? g_y2 : g_y1;
    float* part    = PRE ? g_part2 : g_part1;

    // ---- stage packed weights (81 threads, one LDG each) ----
    if (tid < 81) {
        int co = tid % 3;
        int kx = (tid / 3) % 3;
        int ky = (tid / 9) % 3;
        int ci = tid / 27;
        float wv = __ldg(&w[((co * 3 + ci) * 3 + ky) * 3 + kx]);
        swp[((ci * 3 + ky) * 3 + kx) * 3 + co] = pk2(wv, wv);
    }

    // ---- fill shared tile: vectorized interior + separate halo ----
    const int irow  = tid >> 3;            // 0..31
    const int icolg = (tid & 7) * 8;       // 0..56
    int hr = 0, hc = 0; bool has_halo = tid < 196;
    if (tid < 66)       { hr = 0;            hc = tid; }
    else if (tid < 132) { hr = SH - 1;       hc = tid - 66; }
    else if (tid < 164) { hr = tid - 131;    hc = 0; }        // 1..32
    else if (tid < 196) { hr = tid - 163;    hc = SW - 1; }   // 1..32

    #pragma unroll
    for (int c = 0; c < Cc; c++) {
        float A = 0.f, Bv = 0.f;
        float a0=0,a1=0,a2=0,a3=0,a4=0,a5=0,q0=0,q1=0,q2=0,q3=0;
        if (PRE) {
            A  = g_bn1[c];
            Bv = g_bn1[3 + c];
            const float* A6 = (c == 0) ? ar : ((c == 1) ? ag : ab);
            const float* B4 = (c == 0) ? br : ((c == 1) ? bg : bb);
            a0 = __ldg(&A6[0]); a1 = __ldg(&A6[1]); a2 = __ldg(&A6[2]);
            a3 = __ldg(&A6[3]); a4 = __ldg(&A6[4]); a5 = __ldg(&A6[5]);
            q0 = __ldg(&B4[0]); q1 = __ldg(&B4[1]); q2 = __ldg(&B4[2]); q3 = __ldg(&B4[3]);
        }

        // interior: always in-bounds, 8 contiguous pixels
        {
            float vv[8];
            if (PRE) {
                const __half* base = g_y1 + ((size_t)b * Cc + c) * NPIX;
                const __half* gp = base + (size_t)(h0 + irow) * Ww + (w0 + icolg);
                uint4 raw = *reinterpret_cast<const uint4*>(gp);   // 8 halves
                float2 f0 = __half22float2(*reinterpret_cast<const __half2*>(&raw.x));
                float2 f1 = __half22float2(*reinterpret_cast<const __half2*>(&raw.y));
                float2 f2 = __half22float2(*reinterpret_cast<const __half2*>(&raw.z));
                float2 f3 = __half22float2(*reinterpret_cast<const __half2*>(&raw.w));
                vv[0]=f0.x; vv[1]=f0.y; vv[2]=f1.x; vv[3]=f1.y;
                vv[4]=f2.x; vv[5]=f2.y; vv[6]=f3.x; vv[7]=f3.y;
                #pragma unroll
                for (int j = 0; j < 8; j++) {
                    float t = fmaf(vv[j], A, Bv);
                    vv[j] = ratf(t, a0, a1, a2, a3, a4, a5, q0, q1, q2, q3);
                }
            } else {
                const float* base = xin + ((size_t)b * Cc + c) * NPIX;
                const float* gp = base + (size_t)(h0 + irow) * Ww + (w0 + icolg);
                float4 v0 = *reinterpret_cast<const float4*>(gp);
                float4 v1 = *reinterpret_cast<const float4*>(gp + 4);
                vv[0]=v0.x; vv[1]=v0.y; vv[2]=v0.z; vv[3]=v0.w;
                vv[4]=v1.x; vv[5]=v1.y; vv[6]=v1.z; vv[7]=v1.w;
            }
            float* sp = &s[c][irow + 1][icolg + 1];
            #pragma unroll
            for (int j = 0; j < 8; j++) sp[j] = vv[j];
        }

        // halo: bounds-checked, zero padding stays exactly 0
        if (has_halo) {
            int gh = h0 - 1 + hr;
            int gw = w0 - 1 + hc;
            float v = 0.0f;
            if ((unsigned)gh < Hh && (unsigned)gw < Ww) {
                if (PRE) {
                    const __half* base = g_y1 + ((size_t)b * Cc + c) * NPIX;
                    v = __half2float(base[gh * Ww + gw]);
                    float t = fmaf(v, A, Bv);
                    v = ratf(t, a0, a1, a2, a3, a4, a5, q0, q1, q2, q3);
                } else {
                    const float* base = xin + ((size_t)b * Cc + c) * NPIX;
                    v = base[gh * Ww + gw];
                }
            }
            s[c][hr][hc] = v;
        }
    }
    __syncthreads();

    // ---- compute: 4 wide x 2 tall x 3 out-channels per thread, packed f32x2 ----
    const int tx = tid & 15;
    const int ty = tid >> 4;
    const int col0 = tx * 4;
    const int row0 = ty * 2;

    u64t acc[3][2][2];
    #pragma unroll
    for (int co = 0; co < 3; co++)
        #pragma unroll
        for (int orow = 0; orow < 2; orow++) {
            acc[co][orow][0] = 0ULL;
            acc[co][orow][1] = 0ULL;
        }

    #pragma unroll
    for (int ci = 0; ci < 3; ci++) {
        float2 q[4][3];
        #pragma unroll
        for (int r = 0; r < 4; r++)
            #pragma unroll
            for (int j = 0; j < 3; j++)
                q[r][j] = *reinterpret_cast<const float2*>(&s[ci][row0 + r][col0 + 2 * j]);

        u64t P[4][3], U1[4], U2[4];
        #pragma unroll
        for (int r = 0; r < 4; r++) {
            #pragma unroll
            for (int j = 0; j < 3; j++)
                P[r][j] = pk2(q[r][j].x, q[r][j].y);
            U1[r] = pk2(q[r][0].y, q[r][1].x);
            U2[r] = pk2(q[r][1].y, q[r][2].x);
        }

        #pragma unroll
        for (int ky = 0; ky < 3; ky++)
            #pragma unroll
            for (int kx = 0; kx < 3; kx++)
                #pragma unroll
                for (int co = 0; co < 3; co++) {
                    u64t wp = swp[((ci * 3 + ky) * 3 + kx) * 3 + co];   // LDS.64 broadcast
                    #pragma unroll
                    for (int orow = 0; orow < 2; orow++) {
                        int r = orow + ky;
                        u64t Ap = (kx == 0) ? P[r][0] : ((kx == 1) ? U1[r] : P[r][1]);
                        u64t Bp = (kx == 0) ? P[r][1] : ((kx == 1) ? U2[r] : P[r][2]);
                        acc[co][orow][0] = fma2(wp, Ap, acc[co][orow][0]);
                        acc[co][orow][1] = fma2(wp, Bp, acc[co][orow][1]);
                    }
                }
    }

    // ---- stores (fp16) + packed stats (from fp32 accumulators) ----
    float st[6];
    #pragma unroll
    for (int k = 0; k < 6; k++) st[k] = 0.0f;

    #pragma unroll
    for (int co = 0; co < 3; co++) {
        u64t sm = 0ULL, sq = 0ULL;
        #pragma unroll
        for (int orow = 0; orow < 2; orow++) {
            #pragma unroll
            for (int p = 0; p < 2; p++) {
                u64t a = acc[co][orow][p];
                sm = add2(sm, a);
                sq = fma2(a, a, sq);
            }
            float x0, x1, x2, x3;
            upk2(acc[co][orow][0], x0, x1);
            upk2(acc[co][orow][1], x2, x3);
            union { __half2 h[2]; uint2 u; } cv;
            cv.h[0] = __floats2half2_rn(x0, x1);
            cv.h[1] = __floats2half2_rn(x2, x3);
            size_t off = ((size_t)b * Cc + co) * NPIX
                       + (size_t)(h0 + row0 + orow) * Ww + (w0 + col0);
            *reinterpret_cast<uint2*>(outbuf + off) = cv.u;
        }
        float lo, hi;
        upk2(sm, lo, hi); st[co]     = lo + hi;
        upk2(sq, lo, hi); st[co + 3] = lo + hi;
    }

    // ---- deterministic block reduction ----
    #pragma unroll
    for (int off = 16; off > 0; off >>= 1)
        #pragma unroll
        for (int k = 0; k < 6; k++)
            st[k] += __shfl_down_sync(0xffffffffu, st[k], off);

    const int warp = tid >> 5, lane = tid & 31;
    if (lane == 0)
        #pragma unroll
        for (int k = 0; k < 6; k++) sred[warp][k] = st[k];
    __syncthreads();

    if (tid < 6) {
        float t = 0.0f;
        #pragma unroll
        for (int wp2 = 0; wp2 < 8; wp2++) t += sred[wp2][tid];
        int bid = (blockIdx.z * NB_Y + blockIdx.y) * NB_X + blockIdx.x;
        part[bid * 6 + tid] = t;
    }
    __syncthreads();

    // ---- last-block-done: fold BN (deterministic double reduction) ----
    if (tid == 0) {
        __threadfence();
        unsigned int v = atomicAdd(&g_cnt[PRE ? 1 : 0], 1u);
        isLast = (v == (unsigned)(nblk - 1));
    }
    __syncthreads();

    if (isLast) {
        // reuse the (dead) conv tile smem as double scratch: 256*6*8 = 12KB < 26.9KB
        double* sdd = reinterpret_cast<double*>(&s[0][0][0]);
        double acc6[6] = {0, 0, 0, 0, 0, 0};
        for (int i = tid; i < nblk; i += 256) {
            #pragma unroll
            for (int k = 0; k < 6; k++)
                acc6[k] += (double)part[i * 6 + k];
        }
        #pragma unroll
        for (int k = 0; k < 6; k++) sdd[tid * 6 + k] = acc6[k];
        __syncthreads();

        #pragma unroll
        for (int off = 128; off > 0; off >>= 1) {
            if (tid < off)
                #pragma unroll
                for (int k = 0; k < 6; k++)
                    sdd[tid * 6 + k] += sdd[(tid + off) * 6 + k];
            __syncthreads();
        }

        if (tid < 3) {
            int c = tid;
            float* bn = PRE ? g_bn2 : g_bn1;
            double mean = sdd[c] * invN;
            double var  = sdd[c + 3] * invN - mean * mean;
            float A = gamma[c] / sqrtf((float)var + 1e-5f);
            bn[c]     = A;
            bn[3 + c] = beta[c] - (float)mean * A;
        }
        if (tid == 0) g_cnt[PRE ? 1 : 0] = 0u;   // self-reset for next graph replay
    }
}

// Epilogue: out = rational_c(A2*y2 + B2 + x).
// 4 float4 per thread, block-strided; all loads issued before compute (MLP 8).
#define EPI_Q 4
__global__ __launch_bounds__(256)
void epilogue_kernel(const float* __restrict__ x, float* __restrict__ out,
                     const float* __restrict__ ar, const float* __restrict__ br,
                     const float* __restrict__ ag, const float* __restrict__ bg,
                     const float* __restrict__ ab, const float* __restrict__ bb)
{
    const int base = blockIdx.x * (256 * EPI_Q) + threadIdx.x;

    int c = (base >> 16) % 3;    // same channel for all EPI_Q quads of this thread
    float A  = g_bn2[c];
    float Bv = g_bn2[3 + c];
    const float* A6 = (c == 0) ? ar : ((c == 1) ? ag : ab);
    const float* B4 = (c == 0) ? br : ((c == 1) ? bg : bb);
    float a0 = __ldg(&A6[0]), a1 = __ldg(&A6[1]), a2 = __ldg(&A6[2]);
    float a3 = __ldg(&A6[3]), a4 = __ldg(&A6[4]), a5 = __ldg(&A6[5]);
    float q0 = __ldg(&B4[0]), q1 = __ldg(&B4[1]), q2 = __ldg(&B4[2]), q3 = __ldg(&B4[3]);

    uint2  yraw[EPI_Q];
    float4 xv[EPI_Q];
    #pragma unroll
    for (int k = 0; k < EPI_Q; k++) {
        int i = base + k * 256;
        yraw[k] = reinterpret_cast<const uint2*>(g_y2)[i];
        xv[k]   = reinterpret_cast<const float4*>(x)[i];
    }

    #pragma unroll
    for (int k = 0; k < EPI_Q; k++) {
        float2 y01 = __half22float2(*reinterpret_cast<const __half2*>(&yraw[k].x));
        float2 y23 = __half22float2(*reinterpret_cast<const __half2*>(&yraw[k].y));
        float4 o;
        o.x = ratf(fmaf(y01.x, A, Bv) + xv[k].x, a0, a1, a2, a3, a4, a5, q0, q1, q2, q3);
        o.y = ratf(fmaf(y01.y, A, Bv) + xv[k].y, a0, a1, a2, a3, a4, a5, q0, q1, q2, q3);
        o.z = ratf(fmaf(y23.x, A, Bv) + xv[k].z, a0, a1, a2, a3, a4, a5, q0, q1, q2, q3);
        o.w = ratf(fmaf(y23.y, A, Bv) + xv[k].w, a0, a1, a2, a3, a4, a5, q0, q1, q2, q3);
        reinterpret_cast<float4*>(out)[base + k * 256] = o;
    }
}

extern "C" void kernel_launch(void* const* d_in, const int* in_sizes, int n_in,
                              void* d_out, int out_size)
{
    const float* x  = (const float*)d_in[0];
    const float* w1 = (const float*)d_in[1];
    const float* g1 = (const float*)d_in[2];
    const float* b1 = (const float*)d_in[3];
    const float* ar = (const float*)d_in[4];
    const float* br = (const float*)d_in[5];
    const float* ag = (const float*)d_in[6];
    const float* bg = (const float*)d_in[7];
    const float* ab = (const float*)d_in[8];
    const float* bb = (const float*)d_in[9];
    const float* w2 = (const float*)d_in[10];
    const float* g2 = (const float*)d_in[11];
    const float* b2 = (const float*)d_in[12];
    float* out = (float*)d_out;

    const int B = in_sizes[0] / (Cc * NPIX);   // 64
    const int nblk = NB_X * NB_Y * B;          // 8192
    const double invN = 1.0 / ((double)B * (double)NPIX);

    dim3 grid(NB_X, NB_Y, B), block(256);

    conv_kernel<false><<<grid, block>>>(x, w1, ar, br, ag, bg, ab, bb, g1, b1, nblk, invN);
    conv_kernel<true ><<<grid, block>>>(x, w2, ar, br, ag, bg, ab, bb, g2, b2, nblk, invN);

    int total4 = (B * Cc * NPIX) / 4;            // 12582912, divisible by 1024
    int nb3 = total4 / (256 * EPI_Q);
    epilogue_kernel<<<nb3, 256>>>(x, out, ar, br, ag, bg, ab, bb);
}

// round 13
// speedup vs baseline: 1.1757x; 1.1757x over previous
#include <cuda_runtime.h>
#include <cuda_fp16.h>

// Problem constants
#define Cc 3
#define Hh 512
#define Ww 512
#define NPIX (Hh*Ww)          // 262144
#define MAXB 64

// Tile config: 64 wide x 32 tall, 256 threads, each thread 4w x 2h x 3co
#define TW 64
#define TH 32
#define SW 68                 // padded row stride (usable cols 0..65), 16B-aligned rows
#define SH (TH+2)             // 34
#define NB_X (Ww/TW)          // 8
#define NB_Y (Hh/TH)          // 16
#define NPB (NB_X*NB_Y)       // 128 partials per image
#define NBLK_MAX (NPB*MAXB)   // 8192

// Scratch (fp16 intermediates)
__device__ __half g_y1[(size_t)MAXB*Cc*NPIX];
__device__ __half g_y2[(size_t)MAXB*Cc*NPIX];
__device__ float g_part1[NBLK_MAX*6];
__device__ float g_part2[NBLK_MAX*6];
__device__ double g_mid[MAXB*6];
__device__ float g_bn1[6];
__device__ float g_bn2[6];

// ---- packed f32x2 helpers ----
typedef unsigned long long u64t;
__device__ __forceinline__ u64t pk2(float lo, float hi) {
    u64t r; asm("mov.b64 %0,{%1,%2};" : "=l"(r) : "f"(lo), "f"(hi)); return r;
}
__device__ __forceinline__ void upk2(u64t v, float& lo, float& hi) {
    asm("mov.b64 {%0,%1}, %2;" : "=f"(lo), "=f"(hi) : "l"(v));
}
__device__ __forceinline__ u64t fma2(u64t a, u64t b, u64t c) {
    u64t d; asm("fma.rn.f32x2 %0,%1,%2,%3;" : "=l"(d) : "l"(a), "l"(b), "l"(c)); return d;
}
__device__ __forceinline__ u64t add2(u64t a, u64t b) {
    u64t d; asm("add.rn.f32x2 %0,%1,%2;" : "=l"(d) : "l"(a), "l"(b)); return d;
}

__device__ __forceinline__ float ratf(float x,
    float a0, float a1, float a2, float a3, float a4, float a5,
    float b0, float b1, float b2, float b3)
{
    float P = fmaf(x, fmaf(x, fmaf(x, fmaf(x, fmaf(x, a5, a4), a3), a2), a1), a0);
    float q = fmaf(x, fmaf(x, fmaf(x, b3, b2), b1), b0);
    float Q = 1.0f + fabsf(x * q);
    return __fdividef(P, Q);
}

// Fused conv3x3 (+ optional BN1-affine + rational on input, in-bounds only) + stats.
template<bool PRE>
__global__ __launch_bounds__(256, 5)
void conv_kernel(const float* __restrict__ xin, const float* __restrict__ w,
                 const float* __restrict__ ar, const float* __restrict__ br,
                 const float* __restrict__ ag, const float* __restrict__ bg,
                 const float* __restrict__ ab, const float* __restrict__ bb)
{
    __shared__ __align__(16) float s[Cc][SH][SW];
    __shared__ u64t swp[81];          // packed weights [ci][ky][kx][co]
    __shared__ float sred[8][6];

    const int b  = blockIdx.z;
    const int h0 = blockIdx.y * TH;
    const int w0 = blockIdx.x * TW;
    const int tid = threadIdx.x;

    __half* outbuf = PRE ? g_y2 : g_y1;
    float* part    = PRE ? g_part2 : g_part1;

    // ---- stage packed weights (81 threads, one LDG each) ----
    if (tid < 81) {
        int co = tid % 3;
        int kx = (tid / 3) % 3;
        int ky = (tid / 9) % 3;
        int ci = tid / 27;
        float wv = __ldg(&w[((co * 3 + ci) * 3 + ky) * 3 + kx]);
        swp[((ci * 3 + ky) * 3 + kx) * 3 + co] = pk2(wv, wv);
    }

    // ---- fill shared tile: vectorized interior + separate halo ----
    const int irow  = tid >> 3;            // 0..31
    const int icolg = (tid & 7) * 8;       // 0..56
    int hr = 0, hc = 0; bool has_halo = tid < 196;
    if (tid < 66)       { hr = 0;            hc = tid; }
    else if (tid < 132) { hr = SH - 1;       hc = tid - 66; }
    else if (tid < 164) { hr = tid - 131;    hc = 0; }        // 1..32
    else if (tid < 196) { hr = tid - 163;    hc = 65; }       // 1..32

    #pragma unroll
    for (int c = 0; c < Cc; c++) {
        float A = 0.f, Bv = 0.f;
        float a0=0,a1=0,a2=0,a3=0,a4=0,a5=0,q0=0,q1=0,q2=0,q3=0;
        if (PRE) {
            A  = g_bn1[c];
            Bv = g_bn1[3 + c];
            const float* A6 = (c == 0) ? ar : ((c == 1) ? ag : ab);
            const float* B4 = (c == 0) ? br : ((c == 1) ? bg : bb);
            a0 = __ldg(&A6[0]); a1 = __ldg(&A6[1]); a2 = __ldg(&A6[2]);
            a3 = __ldg(&A6[3]); a4 = __ldg(&A6[4]); a5 = __ldg(&A6[5]);
            q0 = __ldg(&B4[0]); q1 = __ldg(&B4[1]); q2 = __ldg(&B4[2]); q3 = __ldg(&B4[3]);
        }

        // interior: always in-bounds, 8 contiguous pixels
        {
            float vv[8];
            if (PRE) {
                const __half* base = g_y1 + ((size_t)b * Cc + c) * NPIX;
                const __half* gp = base + (size_t)(h0 + irow) * Ww + (w0 + icolg);
                uint4 raw = *reinterpret_cast<const uint4*>(gp);   // 8 halves
                float2 f0 = __half22float2(*reinterpret_cast<const __half2*>(&raw.x));
                float2 f1 = __half22float2(*reinterpret_cast<const __half2*>(&raw.y));
                float2 f2 = __half22float2(*reinterpret_cast<const __half2*>(&raw.z));
                float2 f3 = __half22float2(*reinterpret_cast<const __half2*>(&raw.w));
                vv[0]=f0.x; vv[1]=f0.y; vv[2]=f1.x; vv[3]=f1.y;
                vv[4]=f2.x; vv[5]=f2.y; vv[6]=f3.x; vv[7]=f3.y;
                #pragma unroll
                for (int j = 0; j < 8; j++) {
                    float t = fmaf(vv[j], A, Bv);
                    vv[j] = ratf(t, a0, a1, a2, a3, a4, a5, q0, q1, q2, q3);
                }
            } else {
                const float* base = xin + ((size_t)b * Cc + c) * NPIX;
                const float* gp = base + (size_t)(h0 + irow) * Ww + (w0 + icolg);
                float4 v0 = *reinterpret_cast<const float4*>(gp);
                float4 v1 = *reinterpret_cast<const float4*>(gp + 4);
                vv[0]=v0.x; vv[1]=v0.y; vv[2]=v0.z; vv[3]=v0.w;
                vv[4]=v1.x; vv[5]=v1.y; vv[6]=v1.z; vv[7]=v1.w;
            }
            float* sp = &s[c][irow + 1][icolg + 1];
            #pragma unroll
            for (int j = 0; j < 8; j++) sp[j] = vv[j];
        }

        // halo: bounds-checked, zero padding stays exactly 0
        if (has_halo) {
            int gh = h0 - 1 + hr;
            int gw = w0 - 1 + hc;
            float v = 0.0f;
            if ((unsigned)gh < Hh && (unsigned)gw < Ww) {
                if (PRE) {
                    const __half* base = g_y1 + ((size_t)b * Cc + c) * NPIX;
                    v = __half2float(base[gh * Ww + gw]);
                    float t = fmaf(v, A, Bv);
                    v = ratf(t, a0, a1, a2, a3, a4, a5, q0, q1, q2, q3);
                } else {
                    const float* base = xin + ((size_t)b * Cc + c) * NPIX;
                    v = base[gh * Ww + gw];
                }
            }
            s[c][hr][hc] = v;
        }
    }
    __syncthreads();

    // ---- compute: 4 wide x 2 tall x 3 out-channels per thread, packed f32x2 ----
    const int tx = tid & 15;
    const int ty = tid >> 4;
    const int col0 = tx * 4;
    const int row0 = ty * 2;

    u64t acc[3][2][2];
    #pragma unroll
    for (int co = 0; co < 3; co++)
        #pragma unroll
        for (int orow = 0; orow < 2; orow++) {
            acc[co][orow][0] = 0ULL;
            acc[co][orow][1] = 0ULL;
        }

    #pragma unroll
    for (int ci = 0; ci < 3; ci++) {
        // 4 input rows x cols [col0, col0+7] as 2 aligned float4 (LDS.128)
        float4 qa[4], qb[4];
        #pragma unroll
        for (int r = 0; r < 4; r++) {
            const float* rp = &s[ci][row0 + r][col0];
            qa[r] = *reinterpret_cast<const float4*>(rp);       // cols 0-3
            qb[r] = *reinterpret_cast<const float4*>(rp + 4);   // cols 4-7 (5-7 unused data)
        }

        u64t P[4][3], U1[4], U2[4];
        #pragma unroll
        for (int r = 0; r < 4; r++) {
            P[r][0] = pk2(qa[r].x, qa[r].y);   // cols (0,1)
            P[r][1] = pk2(qa[r].z, qa[r].w);   // cols (2,3)
            P[r][2] = pk2(qb[r].x, qb[r].y);   // cols (4,5)
            U1[r]   = pk2(qa[r].y, qa[r].z);   // cols (1,2)
            U2[r]   = pk2(qa[r].w, qb[r].x);   // cols (3,4)
        }

        #pragma unroll
        for (int ky = 0; ky < 3; ky++)
            #pragma unroll
            for (int kx = 0; kx < 3; kx++)
                #pragma unroll
                for (int co = 0; co < 3; co++) {
                    u64t wp = swp[((ci * 3 + ky) * 3 + kx) * 3 + co];   // LDS.64 broadcast
                    #pragma unroll
                    for (int orow = 0; orow < 2; orow++) {
                        int r = orow + ky;
                        u64t Ap = (kx == 0) ? P[r][0] : ((kx == 1) ? U1[r] : P[r][1]);
                        u64t Bp = (kx == 0) ? P[r][1] : ((kx == 1) ? U2[r] : P[r][2]);
                        acc[co][orow][0] = fma2(wp, Ap, acc[co][orow][0]);
                        acc[co][orow][1] = fma2(wp, Bp, acc[co][orow][1]);
                    }
                }
    }

    // ---- stores (fp16) + packed stats (from fp32 accumulators) ----
    float st[6];
    #pragma unroll
    for (int k = 0; k < 6; k++) st[k] = 0.0f;

    #pragma unroll
    for (int co = 0; co < 3; co++) {
        u64t sm = 0ULL, sq = 0ULL;
        #pragma unroll
        for (int orow = 0; orow < 2; orow++) {
            #pragma unroll
            for (int p = 0; p < 2; p++) {
                u64t a = acc[co][orow][p];
                sm = add2(sm, a);
                sq = fma2(a, a, sq);
            }
            float x0, x1, x2, x3;
            upk2(acc[co][orow][0], x0, x1);
            upk2(acc[co][orow][1], x2, x3);
            union { __half2 h[2]; uint2 u; } cv;
            cv.h[0] = __floats2half2_rn(x0, x1);
            cv.h[1] = __floats2half2_rn(x2, x3);
            size_t off = ((size_t)b * Cc + co) * NPIX
                       + (size_t)(h0 + row0 + orow) * Ww + (w0 + col0);
            *reinterpret_cast<uint2*>(outbuf + off) = cv.u;
        }
        float lo, hi;
        upk2(sm, lo, hi); st[co]     = lo + hi;
        upk2(sq, lo, hi); st[co + 3] = lo + hi;
    }

    // ---- deterministic block reduction ----
    #pragma unroll
    for (int off = 16; off > 0; off >>= 1)
        #pragma unroll
        for (int k = 0; k < 6; k++)
            st[k] += __shfl_down_sync(0xffffffffu, st[k], off);

    const int warp = tid >> 5, lane = tid & 31;
    if (lane == 0)
        #pragma unroll
        for (int k = 0; k < 6; k++) sred[warp][k] = st[k];
    __syncthreads();

    if (tid < 6) {
        float t = 0.0f;
        #pragma unroll
        for (int wp2 = 0; wp2 < 8; wp2++) t += sred[wp2][tid];
        int bid = (blockIdx.z * NB_Y + blockIdx.y) * NB_X + blockIdx.x;
        part[bid * 6 + tid] = t;
    }
}

// Stage A: NPB(=128) partials per image -> 1 double partial per image.
__global__ __launch_bounds__(128)
void reduceA_kernel(int which)
{
    __shared__ double sd[128][6];
    const float* part = which ? g_part2 : g_part1;
    const int tid = threadIdx.x;
    const int base = (blockIdx.x * NPB + tid) * 6;

    #pragma unroll
    for (int k = 0; k < 6; k++) sd[tid][k] = (double)part[base + k];
    __syncthreads();

    #pragma unroll
    for (int off = 64; off > 0; off >>= 1) {
        if (tid < off)
            #pragma unroll
            for (int k = 0; k < 6; k++)
                sd[tid][k] += sd[tid + off][k];
        __syncthreads();
    }

    if (tid < 6) g_mid[blockIdx.x * 6 + tid] = sd[0][tid];
}

// Stage B: reduce B mid-partials, fold BN into per-channel (A, B).
__global__ __launch_bounds__(256)
void reduceB_kernel(const float* __restrict__ gamma, const float* __restrict__ beta,
                    int nmid, double invN, int which)
{
    __shared__ double sd[256][6];
    float* bn = which ? g_bn2 : g_bn1;
    const int tid = threadIdx.x;

    double acc[6] = {0, 0, 0, 0, 0, 0};
    for (int i = tid; i < nmid; i += 256)
        #pragma unroll
        for (int k = 0; k < 6; k++)
            acc[k] += g_mid[i * 6 + k];
    #pragma unroll
    for (int k = 0; k < 6; k++) sd[tid][k] = acc[k];
    __syncthreads();

    #pragma unroll
    for (int off = 128; off > 0; off >>= 1) {
        if (tid < off)
            #pragma unroll
            for (int k = 0; k < 6; k++)
                sd[tid][k] += sd[tid + off][k];
        __syncthreads();
    }

    if (tid < 3) {
        int c = tid;
        double mean = sd[0][c] * invN;
        double var  = sd[0][c + 3] * invN - mean * mean;
        float A = gamma[c] / sqrtf((float)var + 1e-5f);
        bn[c]     = A;
        bn[3 + c] = beta[c] - (float)mean * A;
    }
}

// Epilogue: out = rational_c(A2*y2 + B2 + x).
// 4 float4 per thread, block-strided; all loads issued before compute (MLP 8).
#define EPI_Q 4
__global__ __launch_bounds__(256)
void epilogue_kernel(const float* __restrict__ x, float* __restrict__ out,
                     const float* __restrict__ ar, const float* __restrict__ br,
                     const float* __restrict__ ag, const float* __restrict__ bg,
                     const float* __restrict__ ab, const float* __restrict__ bb)
{
    const int base = blockIdx.x * (256 * EPI_Q) + threadIdx.x;

    int c = (base >> 16) % 3;    // same channel for all EPI_Q quads of this thread
    float A  = g_bn2[c];
    float Bv = g_bn2[3 + c];
    const float* A6 = (c == 0) ? ar : ((c == 1) ? ag : ab);
    const float* B4 = (c == 0) ? br : ((c == 1) ? bg : bb);
    float a0 = __ldg(&A6[0]), a1 = __ldg(&A6[1]), a2 = __ldg(&A6[2]);
    float a3 = __ldg(&A6[3]), a4 = __ldg(&A6[4]), a5 = __ldg(&A6[5]);
    float q0 = __ldg(&B4[0]), q1 = __ldg(&B4[1]), q2 = __ldg(&B4[2]), q3 = __ldg(&B4[3]);

    uint2  yraw[EPI_Q];
    float4 xv[EPI_Q];
    #pragma unroll
    for (int k = 0; k < EPI_Q; k++) {
        int i = base + k * 256;
        yraw[k] = reinterpret_cast<const uint2*>(g_y2)[i];
        xv[k]   = reinterpret_cast<const float4*>(x)[i];
    }

    #pragma unroll
    for (int k = 0; k < EPI_Q; k++) {
        float2 y01 = __half22float2(*reinterpret_cast<const __half2*>(&yraw[k].x));
        float2 y23 = __half22float2(*reinterpret_cast<const __half2*>(&yraw[k].y));
        float4 o;
        o.x = ratf(fmaf(y01.x, A, Bv) + xv[k].x, a0, a1, a2, a3, a4, a5, q0, q1, q2, q3);
        o.y = ratf(fmaf(y01.y, A, Bv) + xv[k].y, a0, a1, a2, a3, a4, a5, q0, q1, q2, q3);
        o.z = ratf(fmaf(y23.x, A, Bv) + xv[k].z, a0, a1, a2, a3, a4, a5, q0, q1, q2, q3);
        o.w = ratf(fmaf(y23.y, A, Bv) + xv[k].w, a0, a1, a2, a3, a4, a5, q0, q1, q2, q3);
        reinterpret_cast<float4*>(out)[base + k * 256] = o;
    }
}

extern "C" void kernel_launch(void* const* d_in, const int* in_sizes, int n_in,
                              void* d_out, int out_size)
{
    const float* x  = (const float*)d_in[0];
    const float* w1 = (const float*)d_in[1];
    const float* g1 = (const float*)d_in[2];
    const float* b1 = (const float*)d_in[3];
    const float* ar = (const float*)d_in[4];
    const float* br = (const float*)d_in[5];
    const float* ag = (const float*)d_in[6];
    const float* bg = (const float*)d_in[7];
    const float* ab = (const float*)d_in[8];
    const float* bb = (const float*)d_in[9];
    const float* w2 = (const float*)d_in[10];
    const float* g2 = (const float*)d_in[11];
    const float* b2 = (const float*)d_in[12];
    float* out = (float*)d_out;

    const int B = in_sizes[0] / (Cc * NPIX);   // 64
    const double invN = 1.0 / ((double)B * (double)NPIX);

    dim3 grid(NB_X, NB_Y, B), block(256);

    conv_kernel<false><<<grid, block>>>(x, w1, ar, br, ag, bg, ab, bb);
    reduceA_kernel<<<B, 128>>>(0);
    reduceB_kernel<<<1, 256>>>(g1, b1, B, invN, 0);
    conv_kernel<true><<<grid, block>>>(x, w2, ar, br, ag, bg, ab, bb);
    reduceA_kernel<<<B, 128>>>(1);
    reduceB_kernel<<<1, 256>>>(g2, b2, B, invN, 1);

    int total4 = (B * Cc * NPIX) / 4;            // 12582912, divisible by 1024
    int nb3 = total4 / (256 * EPI_Q);
    epilogue_kernel<<<nb3, 256>>>(x, out, ar, br, ag, bg, ab, bb);
}

// round 14
// speedup vs baseline: 1.3123x; 1.1162x over previous
#include <cuda_runtime.h>
#include <cuda_fp16.h>

// Problem constants
#define Cc 3
#define Hh 512
#define Ww 512
#define NPIX (Hh*Ww)          // 262144
#define MAXB 64

// Tile config: 64 wide x 32 tall, 256 threads, each thread 4w x 2h x 3co
#define TW 64
#define TH 32
#define SW (TW+2)             // 66
#define SH (TH+2)             // 34
#define NB_X (Ww/TW)          // 8
#define NB_Y (Hh/TH)          // 16
#define NPB (NB_X*NB_Y)       // 128 partials per image
#define NBLK_MAX (NPB*MAXB)   // 8192

// Scratch (fp16 intermediates)
__device__ __half g_y1[(size_t)MAXB*Cc*NPIX];
__device__ __half g_y2[(size_t)MAXB*Cc*NPIX];
__device__ float g_part1[NBLK_MAX*6];
__device__ float g_part2[NBLK_MAX*6];
__device__ double g_mid[MAXB*6];
__device__ float g_bn1[6];
__device__ float g_bn2[6];

// Conv weights in constant memory (uniform/constant port, not LSU)
__constant__ float c_w1[81];
__constant__ float c_w2[81];

// ---- packed f32x2 helpers ----
typedef unsigned long long u64t;
__device__ __forceinline__ u64t pk2(float lo, float hi) {
    u64t r; asm("mov.b64 %0,{%1,%2};" : "=l"(r) : "f"(lo), "f"(hi)); return r;
}
__device__ __forceinline__ void upk2(u64t v, float& lo, float& hi) {
    asm("mov.b64 {%0,%1}, %2;" : "=f"(lo), "=f"(hi) : "l"(v));
}
__device__ __forceinline__ u64t fma2(u64t a, u64t b, u64t c) {
    u64t d; asm("fma.rn.f32x2 %0,%1,%2,%3;" : "=l"(d) : "l"(a), "l"(b), "l"(c)); return d;
}
__device__ __forceinline__ u64t add2(u64t a, u64t b) {
    u64t d; asm("add.rn.f32x2 %0,%1,%2;" : "=l"(d) : "l"(a), "l"(b)); return d;
}

__device__ __forceinline__ float ratf(float x,
    float a0, float a1, float a2, float a3, float a4, float a5,
    float b0, float b1, float b2, float b3)
{
    float P = fmaf(x, fmaf(x, fmaf(x, fmaf(x, fmaf(x, a5, a4), a3), a2), a1), a0);
    float q = fmaf(x, fmaf(x, fmaf(x, b3, b2), b1), b0);
    float Q = 1.0f + fabsf(x * q);
    return __fdividef(P, Q);
}

// Fused conv3x3 (+ optional BN1-affine + rational on input, in-bounds only) + stats.
// Weights come from __constant__ (LDCU / uniform path; frees LSU slots).
template<bool PRE>
__global__ __launch_bounds__(256, 5)
void conv_kernel(const float* __restrict__ xin,
                 const float* __restrict__ ar, const float* __restrict__ br,
                 const float* __restrict__ ag, const float* __restrict__ bg,
                 const float* __restrict__ ab, const float* __restrict__ bb)
{
    __shared__ float s[Cc][SH][SW];
    __shared__ float sred[8][6];

    const int b  = blockIdx.z;
    const int h0 = blockIdx.y * TH;
    const int w0 = blockIdx.x * TW;
    const int tid = threadIdx.x;

    __half* outbuf = PRE ? g_y2 : g_y1;
    float* part    = PRE ? g_part2 : g_part1;
    const float* cw = PRE ? c_w2 : c_w1;

    // ---- fill shared tile: vectorized interior + separate halo ----
    const int irow  = tid >> 3;            // 0..31
    const int icolg = (tid & 7) * 8;       // 0..56
    int hr = 0, hc = 0; bool has_halo = tid < 196;
    if (tid < 66)       { hr = 0;            hc = tid; }
    else if (tid < 132) { hr = SH - 1;       hc = tid - 66; }
    else if (tid < 164) { hr = tid - 131;    hc = 0; }        // 1..32
    else if (tid < 196) { hr = tid - 163;    hc = SW - 1; }   // 1..32

    #pragma unroll
    for (int c = 0; c < Cc; c++) {
        float A = 0.f, Bv = 0.f;
        float a0=0,a1=0,a2=0,a3=0,a4=0,a5=0,q0=0,q1=0,q2=0,q3=0;
        if (PRE) {
            A  = g_bn1[c];
            Bv = g_bn1[3 + c];
            const float* A6 = (c == 0) ? ar : ((c == 1) ? ag : ab);
            const float* B4 = (c == 0) ? br : ((c == 1) ? bg : bb);
            a0 = __ldg(&A6[0]); a1 = __ldg(&A6[1]); a2 = __ldg(&A6[2]);
            a3 = __ldg(&A6[3]); a4 = __ldg(&A6[4]); a5 = __ldg(&A6[5]);
            q0 = __ldg(&B4[0]); q1 = __ldg(&B4[1]); q2 = __ldg(&B4[2]); q3 = __ldg(&B4[3]);
        }

        // interior: always in-bounds, 8 contiguous pixels
        {
            float vv[8];
            if (PRE) {
                const __half* base = g_y1 + ((size_t)b * Cc + c) * NPIX;
                const __half* gp = base + (size_t)(h0 + irow) * Ww + (w0 + icolg);
                uint4 raw = *reinterpret_cast<const uint4*>(gp);   // 8 halves
                float2 f0 = __half22float2(*reinterpret_cast<const __half2*>(&raw.x));
                float2 f1 = __half22float2(*reinterpret_cast<const __half2*>(&raw.y));
                float2 f2 = __half22float2(*reinterpret_cast<const __half2*>(&raw.z));
                float2 f3 = __half22float2(*reinterpret_cast<const __half2*>(&raw.w));
                vv[0]=f0.x; vv[1]=f0.y; vv[2]=f1.x; vv[3]=f1.y;
                vv[4]=f2.x; vv[5]=f2.y; vv[6]=f3.x; vv[7]=f3.y;
                #pragma unroll
                for (int j = 0; j < 8; j++) {
                    float t = fmaf(vv[j], A, Bv);
                    vv[j] = ratf(t, a0, a1, a2, a3, a4, a5, q0, q1, q2, q3);
                }
            } else {
                const float* base = xin + ((size_t)b * Cc + c) * NPIX;
                const float* gp = base + (size_t)(h0 + irow) * Ww + (w0 + icolg);
                float4 v0 = *reinterpret_cast<const float4*>(gp);
                float4 v1 = *reinterpret_cast<const float4*>(gp + 4);
                vv[0]=v0.x; vv[1]=v0.y; vv[2]=v0.z; vv[3]=v0.w;
                vv[4]=v1.x; vv[5]=v1.y; vv[6]=v1.z; vv[7]=v1.w;
            }
            float* sp = &s[c][irow + 1][icolg + 1];
            #pragma unroll
            for (int j = 0; j < 8; j++) sp[j] = vv[j];
        }

        // halo: bounds-checked, zero padding stays exactly 0
        if (has_halo) {
            int gh = h0 - 1 + hr;
            int gw = w0 - 1 + hc;
            float v = 0.0f;
            if ((unsigned)gh < Hh && (unsigned)gw < Ww) {
                if (PRE) {
                    const __half* base = g_y1 + ((size_t)b * Cc + c) * NPIX;
                    v = __half2float(base[gh * Ww + gw]);
                    float t = fmaf(v, A, Bv);
                    v = ratf(t, a0, a1, a2, a3, a4, a5, q0, q1, q2, q3);
                } else {
                    const float* base = xin + ((size_t)b * Cc + c) * NPIX;
                    v = base[gh * Ww + gw];
                }
            }
            s[c][hr][hc] = v;
        }
    }
    __syncthreads();

    // ---- compute: 4 wide x 2 tall x 3 out-channels per thread, packed f32x2 ----
    const int tx = tid & 15;
    const int ty = tid >> 4;
    const int col0 = tx * 4;
    const int row0 = ty * 2;

    u64t acc[3][2][2];
    #pragma unroll
    for (int co = 0; co < 3; co++)
        #pragma unroll
        for (int orow = 0; orow < 2; orow++) {
            acc[co][orow][0] = 0ULL;
            acc[co][orow][1] = 0ULL;
        }

    #pragma unroll
    for (int ci = 0; ci < 3; ci++) {
        float2 q[4][3];
        #pragma unroll
        for (int r = 0; r < 4; r++)
            #pragma unroll
            for (int j = 0; j < 3; j++)
                q[r][j] = *reinterpret_cast<const float2*>(&s[ci][row0 + r][col0 + 2 * j]);

        u64t P[4][3], U1[4], U2[4];
        #pragma unroll
        for (int r = 0; r < 4; r++) {
            #pragma unroll
            for (int j = 0; j < 3; j++)
                P[r][j] = pk2(q[r][j].x, q[r][j].y);
            U1[r] = pk2(q[r][0].y, q[r][1].x);
            U2[r] = pk2(q[r][1].y, q[r][2].x);
        }

        #pragma unroll
        for (int ky = 0; ky < 3; ky++)
            #pragma unroll
            for (int kx = 0; kx < 3; kx++)
                #pragma unroll
                for (int co = 0; co < 3; co++) {
                    float wv = cw[((co * 3 + ci) * 3 + ky) * 3 + kx];  // LDCU (uniform port)
                    u64t wp = pk2(wv, wv);
                    #pragma unroll
                    for (int orow = 0; orow < 2; orow++) {
                        int r = orow + ky;
                        u64t Ap = (kx == 0) ? P[r][0] : ((kx == 1) ? U1[r] : P[r][1]);
                        u64t Bp = (kx == 0) ? P[r][1] : ((kx == 1) ? U2[r] : P[r][2]);
                        acc[co][orow][0] = fma2(wp, Ap, acc[co][orow][0]);
                        acc[co][orow][1] = fma2(wp, Bp, acc[co][orow][1]);
                    }
                }
    }

    // ---- stores (fp16) + packed stats (from fp32 accumulators) ----
    float st[6];
    #pragma unroll
    for (int k = 0; k < 6; k++) st[k] = 0.0f;

    #pragma unroll
    for (int co = 0; co < 3; co++) {
        u64t sm = 0ULL, sq = 0ULL;
        #pragma unroll
        for (int orow = 0; orow < 2; orow++) {
            #pragma unroll
            for (int p = 0; p < 2; p++) {
                u64t a = acc[co][orow][p];
                sm = add2(sm, a);
                sq = fma2(a, a, sq);
            }
            float x0, x1, x2, x3;
            upk2(acc[co][orow][0], x0, x1);
            upk2(acc[co][orow][1], x2, x3);
            union { __half2 h[2]; uint2 u; } cv;
            cv.h[0] = __floats2half2_rn(x0, x1);
            cv.h[1] = __floats2half2_rn(x2, x3);
            size_t off = ((size_t)b * Cc + co) * NPIX
                       + (size_t)(h0 + row0 + orow) * Ww + (w0 + col0);
            *reinterpret_cast<uint2*>(outbuf + off) = cv.u;
        }
        float lo, hi;
        upk2(sm, lo, hi); st[co]     = lo + hi;
        upk2(sq, lo, hi); st[co + 3] = lo + hi;
    }

    // ---- deterministic block reduction ----
    #pragma unroll
    for (int off = 16; off > 0; off >>= 1)
        #pragma unroll
        for (int k = 0; k < 6; k++)
            st[k] += __shfl_down_sync(0xffffffffu, st[k], off);

    const int warp = tid >> 5, lane = tid & 31;
    if (lane == 0)
        #pragma unroll
        for (int k = 0; k < 6; k++) sred[warp][k] = st[k];
    __syncthreads();

    if (tid < 6) {
        float t = 0.0f;
        #pragma unroll
        for (int wp2 = 0; wp2 < 8; wp2++) t += sred[wp2][tid];
        int bid = (blockIdx.z * NB_Y + blockIdx.y) * NB_X + blockIdx.x;
        part[bid * 6 + tid] = t;
    }
}

// Stage A: NPB(=128) partials per image -> 1 double partial per image.
__global__ __launch_bounds__(128)
void reduceA_kernel(int which)
{
    __shared__ double sd[128][6];
    const float* part = which ? g_part2 : g_part1;
    const int tid = threadIdx.x;
    const int base = (blockIdx.x * NPB + tid) * 6;

    #pragma unroll
    for (int k = 0; k < 6; k++) sd[tid][k] = (double)part[base + k];
    __syncthreads();

    #pragma unroll
    for (int off = 64; off > 0; off >>= 1) {
        if (tid < off)
            #pragma unroll
            for (int k = 0; k < 6; k++)
                sd[tid][k] += sd[tid + off][k];
        __syncthreads();
    }

    if (tid < 6) g_mid[blockIdx.x * 6 + tid] = sd[0][tid];
}

// Stage B: reduce B mid-partials, fold BN into per-channel (A, B).
__global__ __launch_bounds__(256)
void reduceB_kernel(const float* __restrict__ gamma, const float* __restrict__ beta,
                    int nmid, double invN, int which)
{
    __shared__ double sd[256][6];
    float* bn = which ? g_bn2 : g_bn1;
    const int tid = threadIdx.x;

    double acc[6] = {0, 0, 0, 0, 0, 0};
    for (int i = tid; i < nmid; i += 256)
        #pragma unroll
        for (int k = 0; k < 6; k++)
            acc[k] += g_mid[i * 6 + k];
    #pragma unroll
    for (int k = 0; k < 6; k++) sd[tid][k] = acc[k];
    __syncthreads();

    #pragma unroll
    for (int off = 128; off > 0; off >>= 1) {
        if (tid < off)
            #pragma unroll
            for (int k = 0; k < 6; k++)
                sd[tid][k] += sd[tid + off][k];
        __syncthreads();
    }

    if (tid < 3) {
        int c = tid;
        double mean = sd[0][c] * invN;
        double var  = sd[0][c + 3] * invN - mean * mean;
        float A = gamma[c] / sqrtf((float)var + 1e-5f);
        bn[c]     = A;
        bn[3 + c] = beta[c] - (float)mean * A;
    }
}

// Epilogue: out = rational_c(A2*y2 + B2 + x).
// 4 float4 per thread, block-strided; all loads issued before compute (MLP 8).
#define EPI_Q 4
__global__ __launch_bounds__(256)
void epilogue_kernel(const float* __restrict__ x, float* __restrict__ out,
                     const float* __restrict__ ar, const float* __restrict__ br,
                     const float* __restrict__ ag, const float* __restrict__ bg,
                     const float* __restrict__ ab, const float* __restrict__ bb)
{
    const int base = blockIdx.x * (256 * EPI_Q) + threadIdx.x;

    int c = (base >> 16) % 3;    // same channel for all EPI_Q quads of this thread
    float A  = g_bn2[c];
    float Bv = g_bn2[3 + c];
    const float* A6 = (c == 0) ? ar : ((c == 1) ? ag : ab);
    const float* B4 = (c == 0) ? br : ((c == 1) ? bg : bb);
    float a0 = __ldg(&A6[0]), a1 = __ldg(&A6[1]), a2 = __ldg(&A6[2]);
    float a3 = __ldg(&A6[3]), a4 = __ldg(&A6[4]), a5 = __ldg(&A6[5]);
    float q0 = __ldg(&B4[0]), q1 = __ldg(&B4[1]), q2 = __ldg(&B4[2]), q3 = __ldg(&B4[3]);

    uint2  yraw[EPI_Q];
    float4 xv[EPI_Q];
    #pragma unroll
    for (int k = 0; k < EPI_Q; k++) {
        int i = base + k * 256;
        yraw[k] = reinterpret_cast<const uint2*>(g_y2)[i];
        xv[k]   = reinterpret_cast<const float4*>(x)[i];
    }

    #pragma unroll
    for (int k = 0; k < EPI_Q; k++) {
        float2 y01 = __half22float2(*reinterpret_cast<const __half2*>(&yraw[k].x));
        float2 y23 = __half22float2(*reinterpret_cast<const __half2*>(&yraw[k].y));
        float4 o;
        o.x = ratf(fmaf(y01.x, A, Bv) + xv[k].x, a0, a1, a2, a3, a4, a5, q0, q1, q2, q3);
        o.y = ratf(fmaf(y01.y, A, Bv) + xv[k].y, a0, a1, a2, a3, a4, a5, q0, q1, q2, q3);
        o.z = ratf(fmaf(y23.x, A, Bv) + xv[k].z, a0, a1, a2, a3, a4, a5, q0, q1, q2, q3);
        o.w = ratf(fmaf(y23.y, A, Bv) + xv[k].w, a0, a1, a2, a3, a4, a5, q0, q1, q2, q3);
        reinterpret_cast<float4*>(out)[base + k * 256] = o;
    }
}

extern "C" void kernel_launch(void* const* d_in, const int* in_sizes, int n_in,
                              void* d_out, int out_size)
{
    const float* x  = (const float*)d_in[0];
    const float* w1 = (const float*)d_in[1];
    const float* g1 = (const float*)d_in[2];
    const float* b1 = (const float*)d_in[3];
    const float* ar = (const float*)d_in[4];
    const float* br = (const float*)d_in[5];
    const float* ag = (const float*)d_in[6];
    const float* bg = (const float*)d_in[7];
    const float* ab = (const float*)d_in[8];
    const float* bb = (const float*)d_in[9];
    const float* w2 = (const float*)d_in[10];
    const float* g2 = (const float*)d_in[11];
    const float* b2 = (const float*)d_in[12];
    float* out = (float*)d_out;

    const int B = in_sizes[0] / (Cc * NPIX);   // 64
    const double invN = 1.0 / ((double)B * (double)NPIX);

    // Stage weights into constant memory (async D2D copies; graph-capturable)
    cudaMemcpyToSymbolAsync(c_w1, w1, 81 * sizeof(float), 0, cudaMemcpyDeviceToDevice);
    cudaMemcpyToSymbolAsync(c_w2, w2, 81 * sizeof(float), 0, cudaMemcpyDeviceToDevice);

    dim3 grid(NB_X, NB_Y, B), block(256);

    conv_kernel<false><<<grid, block>>>(x, ar, br, ag, bg, ab, bb);
    reduceA_kernel<<<B, 128>>>(0);
    reduceB_kernel<<<1, 256>>>(g1, b1, B, invN, 0);
    conv_kernel<true><<<grid, block>>>(x, ar, br, ag, bg, ab, bb);
    reduceA_kernel<<<B, 128>>>(1);
    reduceB_kernel<<<1, 256>>>(g2, b2, B, invN, 1);

    int total4 = (B * Cc * NPIX) / 4;            // 12582912, divisible by 1024
    int nb3 = total4 / (256 * EPI_Q);
    epilogue_kernel<<<nb3, 256>>>(x, out, ar, br, ag, bg, ab, bb);
}